// round 4
// baseline (speedup 1.0000x reference)
#include <cuda_runtime.h>
#include <math.h>

#define N_TOK 65536
#define CDIM 192
#define HIDDEN 768
#define R1 384
#define R2 96

// ---------------- scratch (device globals; no allocation) ----------------
__device__ float g_xn  [N_TOK * CDIM];     // LN1 out, window-ordered
__device__ float g_qkv [N_TOK * 3 * CDIM]; // window-ordered qkv
__device__ float g_attn[N_TOK * CDIM];     // attention out, window-ordered
__device__ float g_x1  [N_TOK * CDIM];     // after attn residual (token order)
__device__ float g_x1n [N_TOK * CDIM];     // LN2 out
__device__ float g_t1  [N_TOK * R1];
__device__ float g_hmid[N_TOK * HIDDEN];
__device__ float g_hconv[N_TOK * HIDDEN];
__device__ float g_t2  [N_TOK * R2];

// window-ordered index p -> token index n  (D=16,H=64,W=64, window 4x8x8)
__device__ __forceinline__ int p_to_n(int p) {
    int win = p >> 8, t = p & 255;
    int wd = win >> 6, wh = (win >> 3) & 7, ww = win & 7;
    int td = t >> 6,  th = (t >> 3) & 7,  tw = t & 7;
    int d = wd * 4 + td, h = wh * 8 + th, w = ww * 8 + tw;
    return (d << 12) + (h << 6) + w;
}

// ---------------- LayerNorm: 1 warp per token ----------------
template <bool PERM_IN>
__global__ void ln_kernel(const float* __restrict__ in, const float* __restrict__ gamma,
                          const float* __restrict__ beta, float* __restrict__ out)
{
    int warp = threadIdx.x >> 5, lane = threadIdx.x & 31;
    int p = blockIdx.x * 8 + warp;
    int n = PERM_IN ? p_to_n(p) : p;
    const float* row = in + (size_t)n * CDIM;
    float v[6]; float s = 0.f, sq = 0.f;
#pragma unroll
    for (int i = 0; i < 6; i++) { float x = row[lane + 32 * i]; v[i] = x; s += x; sq += x * x; }
#pragma unroll
    for (int o = 16; o > 0; o >>= 1) {
        s  += __shfl_xor_sync(0xffffffffu, s,  o);
        sq += __shfl_xor_sync(0xffffffffu, sq, o);
    }
    float mu = s * (1.f / CDIM);
    float var = sq * (1.f / CDIM) - mu * mu;
    float rs = rsqrtf(var + 1e-5f);
    float* orow = out + (size_t)p * CDIM;
#pragma unroll
    for (int i = 0; i < 6; i++) {
        int c = lane + 32 * i;
        orow[c] = (v[i] - mu) * rs * gamma[c] + beta[c];
    }
}

// ---------------- SGEMM: C[M,Nc] = A[M,K] @ B[K,Nc] (+bias) (+resid) ----------------
// BM=128, BN=64, BK=16, 256 threads, 8x4 per thread.
// PERMUTE: output row (and residual row) remapped p->n.
template <bool PERMUTE>
__global__ void sgemm_kernel(const float* __restrict__ A, const float* __restrict__ B,
                             const float* __restrict__ bias, const float* __restrict__ resid,
                             float* __restrict__ C, int M, int Ncols, int K)
{
    const int BM = 128, BN = 64, BK = 16;
    __shared__ float As[BK][BM + 4];
    __shared__ float Bs[BK][BN + 4];
    int tid = threadIdx.x;
    int tx = tid & 15, ty = tid >> 4;
    int row0 = blockIdx.y * BM;
    int col0 = blockIdx.x * BN;
    float acc[8][4];
#pragma unroll
    for (int i = 0; i < 8; i++)
#pragma unroll
        for (int j = 0; j < 4; j++) acc[i][j] = 0.f;

    for (int k0 = 0; k0 < K; k0 += BK) {
        // A tile: 128x16, transposed into As[k][m]
#pragma unroll
        for (int s = tid; s < (BM * BK) / 4; s += 256) {
            int r = s >> 2;
            int c4 = (s & 3) << 2;
            float4 v = *(const float4*)(A + (size_t)(row0 + r) * K + k0 + c4);
            As[c4 + 0][r] = v.x; As[c4 + 1][r] = v.y;
            As[c4 + 2][r] = v.z; As[c4 + 3][r] = v.w;
        }
        // B tile: 16x64
        {
            int r  = tid >> 4;
            int c4 = (tid & 15) << 2;
            int col = col0 + c4;
            float4 v = make_float4(0.f, 0.f, 0.f, 0.f);
            if (col < Ncols) v = *(const float4*)(B + (size_t)(k0 + r) * Ncols + col);
            *(float4*)&Bs[r][c4] = v;
        }
        __syncthreads();
#pragma unroll
        for (int kk = 0; kk < BK; kk++) {
            float4 a0 = *(const float4*)&As[kk][ty * 8];
            float4 a1 = *(const float4*)&As[kk][ty * 8 + 4];
            float4 bv = *(const float4*)&Bs[kk][tx * 4];
            float a[8] = {a0.x, a0.y, a0.z, a0.w, a1.x, a1.y, a1.z, a1.w};
            float b[4] = {bv.x, bv.y, bv.z, bv.w};
#pragma unroll
            for (int i = 0; i < 8; i++)
#pragma unroll
                for (int j = 0; j < 4; j++) acc[i][j] = fmaf(a[i], b[j], acc[i][j]);
        }
        __syncthreads();
    }
#pragma unroll
    for (int i = 0; i < 8; i++) {
        int r = row0 + ty * 8 + i;
        int orow = PERMUTE ? p_to_n(r) : r;
        float* crow = C + (size_t)orow * Ncols;
        const float* rrow = resid ? (resid + (size_t)orow * Ncols) : nullptr;
#pragma unroll
        for (int j = 0; j < 4; j++) {
            int c = col0 + tx * 4 + j;
            if (c < Ncols) {
                float v = acc[i][j];
                if (bias) v += bias[c];
                if (rrow) v += rrow[c];
                crow[c] = v;
            }
        }
    }
}

// ---------------- windowed attention: one block per (head, window) ----------------
// 256 threads; thread i owns query row i. Online softmax; K,V staged in SMEM.
__global__ void __launch_bounds__(256) attn_kernel(const float* __restrict__ rel_bias)
{
    extern __shared__ float sm[];
    float* Ks = sm;            // 256*32
    float* Vs = sm + 8192;     // 256*32
    int*   grp = (int*)(sm + 16384);
    int*   fjs = grp + 256;
    int head = blockIdx.x, win = blockIdx.y;
    int tid = threadIdx.x;
    size_t base = (size_t)(win * 256) * 576 + head * 32;

    // stage Q through SMEM (coalesced), pull own row to regs
    for (int i = tid; i < 8192; i += 256) {
        int r = i >> 5, c = i & 31;
        Ks[i] = g_qkv[base + (size_t)r * 576 + c];
    }
    __syncthreads();
    float q[32];
#pragma unroll
    for (int c = 0; c < 32; c++) q[c] = Ks[tid * 32 + c] * 0.17677669529663687f; // 1/sqrt(32)
    __syncthreads();
    // K, V tiles + per-token metadata
    for (int i = tid; i < 8192; i += 256) {
        int r = i >> 5, c = i & 31;
        Ks[i] = g_qkv[base + 192 + (size_t)r * 576 + c];
        Vs[i] = g_qkv[base + 384 + (size_t)r * 576 + c];
    }
    {
        int t = tid;
        int wd = win >> 6, wh = (win >> 3) & 7, ww = win & 7;
        int td = t >> 6, th = (t >> 3) & 7, tw = t & 7;
        int d = wd * 4 + td, h = wh * 8 + th, w = ww * 8 + tw;
        int gd = (d + 2) & 15, gh = (h + 4) & 63, gw = (w + 4) & 63; // shifted-mask group
        grp[t] = (gd >> 2) * 64 + (gh >> 3) * 8 + (gw >> 3);
        fjs[t] = td * 225 + th * 15 + tw;                            // rel-index component
    }
    __syncthreads();

    int gi = grp[tid];
    int fi = fjs[tid] + 787; // 3*225 + 7*15 + 7
    float m = -1e30f, l = 0.f;
    float o[32];
#pragma unroll
    for (int c = 0; c < 32; c++) o[c] = 0.f;

    for (int j = 0; j < 256; j++) {
        const float4* kr = (const float4*)(Ks + j * 32);
        float s = 0.f;
#pragma unroll
        for (int c4 = 0; c4 < 8; c4++) {
            float4 kv = kr[c4];
            s = fmaf(q[c4 * 4 + 0], kv.x, s); s = fmaf(q[c4 * 4 + 1], kv.y, s);
            s = fmaf(q[c4 * 4 + 2], kv.z, s); s = fmaf(q[c4 * 4 + 3], kv.w, s);
        }
        int ridx = fi - fjs[j];
        s += __ldg(&rel_bias[ridx * 6 + head]);
        if (grp[j] != gi) s -= 100.f;

        if (s > m) {
            float corr = __expf(m - s);
            l *= corr;
#pragma unroll
            for (int c = 0; c < 32; c++) o[c] *= corr;
            m = s;
        }
        float pexp = __expf(s - m);
        l += pexp;
        const float4* vr = (const float4*)(Vs + j * 32);
#pragma unroll
        for (int c4 = 0; c4 < 8; c4++) {
            float4 vv = vr[c4];
            o[c4 * 4 + 0] = fmaf(pexp, vv.x, o[c4 * 4 + 0]);
            o[c4 * 4 + 1] = fmaf(pexp, vv.y, o[c4 * 4 + 1]);
            o[c4 * 4 + 2] = fmaf(pexp, vv.z, o[c4 * 4 + 2]);
            o[c4 * 4 + 3] = fmaf(pexp, vv.w, o[c4 * 4 + 3]);
        }
    }
    float inv = 1.f / l;
    float4* ow = (float4*)(g_attn + (size_t)(win * 256 + tid) * 192 + head * 32);
#pragma unroll
    for (int c4 = 0; c4 < 8; c4++)
        ow[c4] = make_float4(o[c4 * 4 + 0] * inv, o[c4 * 4 + 1] * inv,
                             o[c4 * 4 + 2] * inv, o[c4 * 4 + 3] * inv);
}

// ---------------- depthwise conv3d 3x3x3 + bias + exact GELU ----------------
// One block (256 threads) per (token n, channel-chunk of 256). All threads share n.
__global__ void dwconv_gelu_kernel(const float* __restrict__ wgt, const float* __restrict__ bias)
{
    __shared__ float sw[256 * 27];
    int tid = threadIdx.x;
    int c0 = (int)(((long long)blockIdx.x * 256) % 768);
    for (int i = tid; i < 256 * 27; i += 256) sw[i] = wgt[c0 * 27 + i];
    __syncthreads();

    int idx = blockIdx.x * 256 + tid;     // < 65536*768 < 2^31? no: 50.3M, fits
    int c = c0 + tid;
    int n = idx / 768;
    int w = n & 63, h = (n >> 6) & 63, d = n >> 12;
    float acc = bias[c];
    const float* wp = sw + tid * 27;
#pragma unroll
    for (int kd = -1; kd <= 1; kd++) {
        int dd = d + kd; if ((unsigned)dd >= 16u) continue;
#pragma unroll
        for (int kh = -1; kh <= 1; kh++) {
            int hh = h + kh; if ((unsigned)hh >= 64u) continue;
#pragma unroll
            for (int kw = -1; kw <= 1; kw++) {
                int ww2 = w + kw; if ((unsigned)ww2 >= 64u) continue;
                int nn = (dd << 12) + (hh << 6) + ww2;
                acc = fmaf(g_hmid[(size_t)nn * 768 + c],
                           wp[(kd + 1) * 9 + (kh + 1) * 3 + (kw + 1)], acc);
            }
        }
    }
    g_hconv[idx] = 0.5f * acc * (1.f + erff(acc * 0.70710678118654752440f));
}

// ---------------- host ----------------
extern "C" void kernel_launch(void* const* d_in, const int* in_sizes, int n_in,
                              void* d_out, int out_size)
{
    (void)in_sizes; (void)n_in; (void)out_size;
    const float* x       = (const float*)d_in[0];
    const float* n1g     = (const float*)d_in[1];
    const float* n1b     = (const float*)d_in[2];
    const float* qkv_w   = (const float*)d_in[3];
    const float* qkv_b   = (const float*)d_in[4];
    const float* rel_b   = (const float*)d_in[5];
    const float* proj_w  = (const float*)d_in[6];
    const float* proj_b  = (const float*)d_in[7];
    const float* n2g     = (const float*)d_in[8];
    const float* n2b     = (const float*)d_in[9];
    const float* fc1_A   = (const float*)d_in[10];
    const float* fc1_Bw  = (const float*)d_in[11];
    const float* fc1_Bb  = (const float*)d_in[12];
    const float* dw_w    = (const float*)d_in[13];
    const float* dw_b    = (const float*)d_in[14];
    const float* fc2_A   = (const float*)d_in[15];
    const float* fc2_Bw  = (const float*)d_in[16];
    const float* fc2_Bb  = (const float*)d_in[17];
    float* out = (float*)d_out;

    void *p_xn, *p_qkv, *p_attn, *p_x1, *p_x1n, *p_t1, *p_hmid, *p_hconv, *p_t2;
    cudaGetSymbolAddress(&p_xn, g_xn);     cudaGetSymbolAddress(&p_qkv, g_qkv);
    cudaGetSymbolAddress(&p_attn, g_attn); cudaGetSymbolAddress(&p_x1, g_x1);
    cudaGetSymbolAddress(&p_x1n, g_x1n);   cudaGetSymbolAddress(&p_t1, g_t1);
    cudaGetSymbolAddress(&p_hmid, g_hmid); cudaGetSymbolAddress(&p_hconv, g_hconv);
    cudaGetSymbolAddress(&p_t2, g_t2);

    // 1) LN1 (read-permuted into window order)
    ln_kernel<true><<<N_TOK / 8, 256>>>(x, n1g, n1b, (float*)p_xn);
    // 2) QKV gemm
    sgemm_kernel<false><<<dim3((576 + 63) / 64, N_TOK / 128), 256>>>(
        (const float*)p_xn, qkv_w, qkv_b, nullptr, (float*)p_qkv, N_TOK, 576, 192);
    // 3) attention
    const int SMEM_ATTN = (8192 + 8192 + 256 + 256) * 4;
    cudaFuncSetAttribute(attn_kernel, cudaFuncAttributeMaxDynamicSharedMemorySize, SMEM_ATTN);
    attn_kernel<<<dim3(6, 256), 256, SMEM_ATTN>>>(rel_b);
    // 4) proj + residual (+ un-window permute on write)
    sgemm_kernel<true><<<dim3((192 + 63) / 64, N_TOK / 128), 256>>>(
        (const float*)p_attn, proj_w, proj_b, x, (float*)p_x1, N_TOK, 192, 192);
    // 5) LN2
    ln_kernel<false><<<N_TOK / 8, 256>>>((const float*)p_x1, n2g, n2b, (float*)p_x1n);
    // 6) fc1 low-rank
    sgemm_kernel<false><<<dim3((384 + 63) / 64, N_TOK / 128), 256>>>(
        (const float*)p_x1n, fc1_A, nullptr, nullptr, (float*)p_t1, N_TOK, 384, 192);
    sgemm_kernel<false><<<dim3((768 + 63) / 64, N_TOK / 128), 256>>>(
        (const float*)p_t1, fc1_Bw, fc1_Bb, nullptr, (float*)p_hmid, N_TOK, 768, 384);
    // 7) depthwise conv + GELU
    dwconv_gelu_kernel<<<(N_TOK * (HIDDEN / 256)), 256>>>(dw_w, dw_b);
    // 8) fc2 low-rank + final residual
    sgemm_kernel<false><<<dim3((96 + 63) / 64, N_TOK / 128), 256>>>(
        (const float*)p_hconv, fc2_A, nullptr, nullptr, (float*)p_t2, N_TOK, 96, 768);
    sgemm_kernel<false><<<dim3((192 + 63) / 64, N_TOK / 128), 256>>>(
        (const float*)p_t2, fc2_Bw, fc2_Bb, (const float*)p_x1, out, N_TOK, 192, 96);
}

// round 9
// speedup vs baseline: 1.6898x; 1.6898x over previous
#include <cuda_runtime.h>
#include <cuda_bf16.h>
#include <math.h>
#include <cstdint>

#define N_TOK 65536
#define CDIM 192
#define HIDDEN 768
#define R1 384
#define R2 96

// ---------------- scratch (device globals; no allocation) ----------------
__device__ float g_qkv [N_TOK * 3 * CDIM]; // window-ordered qkv (fp32 for softmax accuracy)
__device__ float g_x1  [N_TOK * CDIM];     // after attn residual (token order, fp32)
__device__ float g_hmid[N_TOK * HIDDEN];   // fc1 out (fp32 for dwconv)

__device__ __nv_bfloat16 g_xn_b   [N_TOK * CDIM];   // LN1 out (window order)
__device__ __nv_bfloat16 g_x1n_b  [N_TOK * CDIM];   // LN2 out
__device__ __nv_bfloat16 g_attn_b [N_TOK * CDIM];   // attention out (window order)
__device__ __nv_bfloat16 g_t1_b   [N_TOK * R1];
__device__ __nv_bfloat16 g_hconv_b[N_TOK * HIDDEN];
__device__ __nv_bfloat16 g_t2_b   [N_TOK * R2];

// transposed bf16 weights Wt[N][K]
__device__ __nv_bfloat16 g_wqkv_t [576 * 192];
__device__ __nv_bfloat16 g_wproj_t[192 * 192];
__device__ __nv_bfloat16 g_wfc1A_t[384 * 192];
__device__ __nv_bfloat16 g_wfc1B_t[768 * 384];
__device__ __nv_bfloat16 g_wfc2A_t[96 * 768];
__device__ __nv_bfloat16 g_wfc2B_t[192 * 96];

// window-ordered index p -> token index n  (D=16,H=64,W=64, window 4x8x8)
__device__ __forceinline__ int p_to_n(int p) {
    int win = p >> 8, t = p & 255;
    int wd = win >> 6, wh = (win >> 3) & 7, ww = win & 7;
    int td = t >> 6,  th = (t >> 3) & 7,  tw = t & 7;
    int d = wd * 4 + td, h = wh * 8 + th, w = ww * 8 + tw;
    return (d << 12) + (h << 6) + w;
}

// ---------------- weight convert + transpose: W[K,N] fp32 -> Wt[N,K] bf16 ----------------
__global__ void convert_wt(const float* __restrict__ W, __nv_bfloat16* __restrict__ Wt,
                           int K, int N)
{
    int idx = blockIdx.x * 256 + threadIdx.x;
    if (idx < K * N) {
        int k = idx / N, n = idx - k * N;
        Wt[n * K + k] = __float2bfloat16(W[idx]);
    }
}

// ---------------- LayerNorm: 1 warp per token, bf16 out ----------------
template <bool PERM_IN>
__global__ void ln_kernel(const float* __restrict__ in, const float* __restrict__ gamma,
                          const float* __restrict__ beta, __nv_bfloat16* __restrict__ out)
{
    int warp = threadIdx.x >> 5, lane = threadIdx.x & 31;
    int p = blockIdx.x * 8 + warp;
    int n = PERM_IN ? p_to_n(p) : p;
    const float* row = in + (size_t)n * CDIM;
    float v[6]; float s = 0.f, sq = 0.f;
#pragma unroll
    for (int i = 0; i < 6; i++) { float x = row[lane + 32 * i]; v[i] = x; s += x; sq += x * x; }
#pragma unroll
    for (int o = 16; o > 0; o >>= 1) {
        s  += __shfl_xor_sync(0xffffffffu, s,  o);
        sq += __shfl_xor_sync(0xffffffffu, sq, o);
    }
    float mu = s * (1.f / CDIM);
    float var = sq * (1.f / CDIM) - mu * mu;
    float rs = rsqrtf(var + 1e-5f);
    __nv_bfloat16* orow = out + (size_t)p * CDIM;
#pragma unroll
    for (int i = 0; i < 6; i++) {
        int c = lane + 32 * i;
        orow[c] = __float2bfloat16((v[i] - mu) * rs * gamma[c] + beta[c]);
    }
}

// ---------------- bf16 tensor-core GEMM ----------------
// C[M,Nc] (fp32, optional) / Cb[M,Nc] (bf16, optional) = A[M,K]bf16 @ Wt[Nc,K]bf16^T
// + bias (fp32) + resid (fp32). PERMUTE remaps output row p->n (and resid read).
// BM=128 BN=64 BK=32; 8 warps (4 m x 2 n), warp tile 32x32 = 2x4 m16n8k16 MMAs.
#define SM_STRIDE32 20   // 40 bf16 per row = 20 words (conflict-free fragment reads)

#define MMA16816(d, a, b)                                                     \
    asm volatile("mma.sync.aligned.m16n8k16.row.col.f32.bf16.bf16.f32 "       \
                 "{%0,%1,%2,%3}, {%4,%5,%6,%7}, {%8,%9}, {%0,%1,%2,%3};"      \
                 : "+f"(d[0]), "+f"(d[1]), "+f"(d[2]), "+f"(d[3])             \
                 : "r"(a[0]), "r"(a[1]), "r"(a[2]), "r"(a[3]),                 \
                   "r"(b[0]), "r"(b[1]))

template <bool PERMUTE>
__global__ void __launch_bounds__(256) bgemm_kernel(
    const __nv_bfloat16* __restrict__ A, const __nv_bfloat16* __restrict__ Wt,
    const float* __restrict__ bias, const float* __restrict__ resid,
    float* __restrict__ C, __nv_bfloat16* __restrict__ Cb,
    int M, int Ncols, int K)
{
    __shared__ unsigned int As32[128 * SM_STRIDE32];
    __shared__ unsigned int Bs32[64 * SM_STRIDE32];

    int tid  = threadIdx.x;
    int lane = tid & 31;
    int warp = tid >> 5;
    int wm = warp >> 1;           // 0..3, 32 rows each
    int wn = warp & 1;            // 0..1, 32 cols each
    int g  = lane >> 2;           // 0..7
    int tg = lane & 3;            // 0..3

    int row0 = blockIdx.y * 128;
    int col0 = blockIdx.x * 64;

    float acc[2][4][4];
#pragma unroll
    for (int t = 0; t < 2; t++)
#pragma unroll
        for (int u = 0; u < 4; u++)
#pragma unroll
            for (int i = 0; i < 4; i++) acc[t][u][i] = 0.f;

    // A-tile global load mapping: 512 16B segments, 2 per thread
    // B-tile: 256 16B segments, 1 per thread
    int br = tid >> 2, bseg = tid & 3;
    int bcol = col0 + br;

    for (int k0 = 0; k0 < K; k0 += 32) {
#pragma unroll
        for (int i = 0; i < 2; i++) {
            int s = tid + i * 256;
            int r = s >> 2, seg = s & 3;
            uint4 v = *(const uint4*)(A + (size_t)(row0 + r) * K + k0 + seg * 8);
            ((uint4*)As32)[r * 5 + seg] = v;
        }
        {
            uint4 v = make_uint4(0u, 0u, 0u, 0u);
            if (bcol < Ncols)
                v = *(const uint4*)(Wt + (size_t)bcol * K + k0 + bseg * 8);
            ((uint4*)Bs32)[br * 5 + bseg] = v;
        }
        __syncthreads();

#pragma unroll
        for (int ks = 0; ks < 2; ks++) {
            unsigned int a[2][4], b[4][2];
#pragma unroll
            for (int t = 0; t < 2; t++) {
                int base = (wm * 32 + t * 16 + g) * SM_STRIDE32 + ks * 8 + tg;
                a[t][0] = As32[base];
                a[t][1] = As32[base + 8 * SM_STRIDE32];
                a[t][2] = As32[base + 4];
                a[t][3] = As32[base + 8 * SM_STRIDE32 + 4];
            }
#pragma unroll
            for (int u = 0; u < 4; u++) {
                int base = (wn * 32 + u * 8 + g) * SM_STRIDE32 + ks * 8 + tg;
                b[u][0] = Bs32[base];
                b[u][1] = Bs32[base + 4];
            }
#pragma unroll
            for (int t = 0; t < 2; t++)
#pragma unroll
                for (int u = 0; u < 4; u++)
                    MMA16816(acc[t][u], a[t], b[u]);
        }
        __syncthreads();
    }

    // epilogue
#pragma unroll
    for (int t = 0; t < 2; t++) {
        int rlo = row0 + wm * 32 + t * 16 + g;
#pragma unroll
        for (int h2 = 0; h2 < 2; h2++) {
            int r = rlo + h2 * 8;
            int orow = PERMUTE ? p_to_n(r) : r;
            size_t ro = (size_t)orow * Ncols;
#pragma unroll
            for (int u = 0; u < 4; u++) {
                int c = col0 + wn * 32 + u * 8 + 2 * tg;
                if (c < Ncols) {
                    float v0 = acc[t][u][h2 * 2 + 0];
                    float v1 = acc[t][u][h2 * 2 + 1];
                    if (bias)  { v0 += bias[c]; v1 += bias[c + 1]; }
                    if (resid) { float2 rv = *(const float2*)(resid + ro + c);
                                 v0 += rv.x; v1 += rv.y; }
                    if (C)  *(float2*)(C + ro + c) = make_float2(v0, v1);
                    if (Cb) *(__nv_bfloat162*)(Cb + ro + c) = __floats2bfloat162_rn(v0, v1);
                }
            }
        }
    }
}

// ---------------- windowed attention: one block per (head, window) ----------------
__global__ void __launch_bounds__(256) attn_kernel(const float* __restrict__ rel_bias)
{
    extern __shared__ float sm[];
    float* Ks = sm;            // 256*32
    float* Vs = sm + 8192;     // 256*32
    int*   grp = (int*)(sm + 16384);
    int*   fjs = grp + 256;
    int head = blockIdx.x, win = blockIdx.y;
    int tid = threadIdx.x;
    size_t base = (size_t)(win * 256) * 576 + head * 32;

    for (int i = tid; i < 8192; i += 256) {
        int r = i >> 5, c = i & 31;
        Ks[i] = g_qkv[base + (size_t)r * 576 + c];
    }
    __syncthreads();
    float q[32];
#pragma unroll
    for (int c = 0; c < 32; c++) q[c] = Ks[tid * 32 + c] * 0.17677669529663687f;
    __syncthreads();
    for (int i = tid; i < 8192; i += 256) {
        int r = i >> 5, c = i & 31;
        Ks[i] = g_qkv[base + 192 + (size_t)r * 576 + c];
        Vs[i] = g_qkv[base + 384 + (size_t)r * 576 + c];
    }
    {
        int t = tid;
        int wd = win >> 6, wh = (win >> 3) & 7, ww = win & 7;
        int td = t >> 6, th = (t >> 3) & 7, tw = t & 7;
        int d = wd * 4 + td, h = wh * 8 + th, w = ww * 8 + tw;
        int gd = (d + 2) & 15, gh = (h + 4) & 63, gw = (w + 4) & 63;
        grp[t] = (gd >> 2) * 64 + (gh >> 3) * 8 + (gw >> 3);
        fjs[t] = td * 225 + th * 15 + tw;
    }
    __syncthreads();

    int gi = grp[tid];
    int fi = fjs[tid] + 787;
    float m = -1e30f, l = 0.f;
    float o[32];
#pragma unroll
    for (int c = 0; c < 32; c++) o[c] = 0.f;

    for (int j = 0; j < 256; j++) {
        const float4* kr = (const float4*)(Ks + j * 32);
        float s = 0.f;
#pragma unroll
        for (int c4 = 0; c4 < 8; c4++) {
            float4 kv = kr[c4];
            s = fmaf(q[c4 * 4 + 0], kv.x, s); s = fmaf(q[c4 * 4 + 1], kv.y, s);
            s = fmaf(q[c4 * 4 + 2], kv.z, s); s = fmaf(q[c4 * 4 + 3], kv.w, s);
        }
        int ridx = fi - fjs[j];
        s += __ldg(&rel_bias[ridx * 6 + head]);
        if (grp[j] != gi) s -= 100.f;

        if (s > m) {
            float corr = __expf(m - s);
            l *= corr;
#pragma unroll
            for (int c = 0; c < 32; c++) o[c] *= corr;
            m = s;
        }
        float pexp = __expf(s - m);
        l += pexp;
        const float4* vr = (const float4*)(Vs + j * 32);
#pragma unroll
        for (int c4 = 0; c4 < 8; c4++) {
            float4 vv = vr[c4];
            o[c4 * 4 + 0] = fmaf(pexp, vv.x, o[c4 * 4 + 0]);
            o[c4 * 4 + 1] = fmaf(pexp, vv.y, o[c4 * 4 + 1]);
            o[c4 * 4 + 2] = fmaf(pexp, vv.z, o[c4 * 4 + 2]);
            o[c4 * 4 + 3] = fmaf(pexp, vv.w, o[c4 * 4 + 3]);
        }
    }
    float inv = 1.f / l;
    __nv_bfloat162* ow = (__nv_bfloat162*)(g_attn_b + (size_t)(win * 256 + tid) * 192 + head * 32);
#pragma unroll
    for (int c2 = 0; c2 < 16; c2++)
        ow[c2] = __floats2bfloat162_rn(o[2 * c2] * inv, o[2 * c2 + 1] * inv);
}

// ---------------- depthwise conv3d 3x3x3 + bias + exact GELU (bf16 out) ----------------
__global__ void dwconv_gelu_kernel(const float* __restrict__ wgt, const float* __restrict__ bias)
{
    __shared__ float sw[256 * 27];
    int tid = threadIdx.x;
    int c0 = (int)(((long long)blockIdx.x * 256) % 768);
    for (int i = tid; i < 256 * 27; i += 256) sw[i] = wgt[c0 * 27 + i];
    __syncthreads();

    int idx = blockIdx.x * 256 + tid;
    int c = c0 + tid;
    int n = idx / 768;
    int w = n & 63, h = (n >> 6) & 63, d = n >> 12;
    float acc = bias[c];
    const float* wp = sw + tid * 27;
#pragma unroll
    for (int kd = -1; kd <= 1; kd++) {
        int dd = d + kd; if ((unsigned)dd >= 16u) continue;
#pragma unroll
        for (int kh = -1; kh <= 1; kh++) {
            int hh = h + kh; if ((unsigned)hh >= 64u) continue;
#pragma unroll
            for (int kw = -1; kw <= 1; kw++) {
                int ww2 = w + kw; if ((unsigned)ww2 >= 64u) continue;
                int nn = (dd << 12) + (hh << 6) + ww2;
                acc = fmaf(g_hmid[(size_t)nn * 768 + c],
                           wp[(kd + 1) * 9 + (kh + 1) * 3 + (kw + 1)], acc);
            }
        }
    }
    float gel = 0.5f * acc * (1.f + erff(acc * 0.70710678118654752440f));
    g_hconv_b[idx] = __float2bfloat16(gel);
}

// ---------------- host ----------------
extern "C" void kernel_launch(void* const* d_in, const int* in_sizes, int n_in,
                              void* d_out, int out_size)
{
    (void)in_sizes; (void)n_in; (void)out_size;
    const float* x       = (const float*)d_in[0];
    const float* n1g     = (const float*)d_in[1];
    const float* n1b     = (const float*)d_in[2];
    const float* qkv_w   = (const float*)d_in[3];
    const float* qkv_b   = (const float*)d_in[4];
    const float* rel_b   = (const float*)d_in[5];
    const float* proj_w  = (const float*)d_in[6];
    const float* proj_b  = (const float*)d_in[7];
    const float* n2g     = (const float*)d_in[8];
    const float* n2b     = (const float*)d_in[9];
    const float* fc1_A   = (const float*)d_in[10];
    const float* fc1_Bw  = (const float*)d_in[11];
    const float* fc1_Bb  = (const float*)d_in[12];
    const float* dw_w    = (const float*)d_in[13];
    const float* dw_b    = (const float*)d_in[14];
    const float* fc2_A   = (const float*)d_in[15];
    const float* fc2_Bw  = (const float*)d_in[16];
    const float* fc2_Bb  = (const float*)d_in[17];
    float* out = (float*)d_out;

    void *p_qkv, *p_x1, *p_hmid;
    void *p_xnb, *p_x1nb, *p_attnb, *p_t1b, *p_hcb, *p_t2b;
    void *p_wqkv, *p_wproj, *p_wf1a, *p_wf1b, *p_wf2a, *p_wf2b;
    cudaGetSymbolAddress(&p_qkv, g_qkv);   cudaGetSymbolAddress(&p_x1, g_x1);
    cudaGetSymbolAddress(&p_hmid, g_hmid);
    cudaGetSymbolAddress(&p_xnb, g_xn_b);  cudaGetSymbolAddress(&p_x1nb, g_x1n_b);
    cudaGetSymbolAddress(&p_attnb, g_attn_b); cudaGetSymbolAddress(&p_t1b, g_t1_b);
    cudaGetSymbolAddress(&p_hcb, g_hconv_b);  cudaGetSymbolAddress(&p_t2b, g_t2_b);
    cudaGetSymbolAddress(&p_wqkv, g_wqkv_t);  cudaGetSymbolAddress(&p_wproj, g_wproj_t);
    cudaGetSymbolAddress(&p_wf1a, g_wfc1A_t); cudaGetSymbolAddress(&p_wf1b, g_wfc1B_t);
    cudaGetSymbolAddress(&p_wf2a, g_wfc2A_t); cudaGetSymbolAddress(&p_wf2b, g_wfc2B_t);

    // 0) weight convert + transpose (tiny)
    convert_wt<<<(192*576 + 255)/256, 256>>>(qkv_w,  (__nv_bfloat16*)p_wqkv, 192, 576);
    convert_wt<<<(192*192 + 255)/256, 256>>>(proj_w, (__nv_bfloat16*)p_wproj, 192, 192);
    convert_wt<<<(192*384 + 255)/256, 256>>>(fc1_A,  (__nv_bfloat16*)p_wf1a, 192, 384);
    convert_wt<<<(384*768 + 255)/256, 256>>>(fc1_Bw, (__nv_bfloat16*)p_wf1b, 384, 768);
    convert_wt<<<(768*96  + 255)/256, 256>>>(fc2_A,  (__nv_bfloat16*)p_wf2a, 768, 96);
    convert_wt<<<(96*192  + 255)/256, 256>>>(fc2_Bw, (__nv_bfloat16*)p_wf2b, 96, 192);

    // 1) LN1 (read-permuted into window order), bf16 out
    ln_kernel<true><<<N_TOK / 8, 256>>>(x, n1g, n1b, (__nv_bfloat16*)p_xnb);
    // 2) QKV gemm -> fp32
    bgemm_kernel<false><<<dim3(9, N_TOK / 128), 256>>>(
        (const __nv_bfloat16*)p_xnb, (const __nv_bfloat16*)p_wqkv, qkv_b, nullptr,
        (float*)p_qkv, nullptr, N_TOK, 576, 192);
    // 3) attention -> bf16
    const int SMEM_ATTN = (8192 + 8192 + 256 + 256) * 4;
    cudaFuncSetAttribute(attn_kernel, cudaFuncAttributeMaxDynamicSharedMemorySize, SMEM_ATTN);
    attn_kernel<<<dim3(6, 256), 256, SMEM_ATTN>>>(rel_b);
    // 4) proj + residual (+ un-window permute on write) -> fp32
    bgemm_kernel<true><<<dim3(3, N_TOK / 128), 256>>>(
        (const __nv_bfloat16*)p_attnb, (const __nv_bfloat16*)p_wproj, proj_b, x,
        (float*)p_x1, nullptr, N_TOK, 192, 192);
    // 5) LN2 -> bf16
    ln_kernel<false><<<N_TOK / 8, 256>>>((const float*)p_x1, n2g, n2b, (__nv_bfloat16*)p_x1nb);
    // 6) fc1 low-rank
    bgemm_kernel<false><<<dim3(6, N_TOK / 128), 256>>>(
        (const __nv_bfloat16*)p_x1nb, (const __nv_bfloat16*)p_wf1a, nullptr, nullptr,
        nullptr, (__nv_bfloat16*)p_t1b, N_TOK, 384, 192);
    bgemm_kernel<false><<<dim3(12, N_TOK / 128), 256>>>(
        (const __nv_bfloat16*)p_t1b, (const __nv_bfloat16*)p_wf1b, fc1_Bb, nullptr,
        (float*)p_hmid, nullptr, N_TOK, 768, 384);
    // 7) depthwise conv + GELU -> bf16
    dwconv_gelu_kernel<<<(N_TOK * (HIDDEN / 256)), 256>>>(dw_w, dw_b);
    // 8) fc2 low-rank + final residual
    bgemm_kernel<false><<<dim3(2, N_TOK / 128), 256>>>(
        (const __nv_bfloat16*)p_hcb, (const __nv_bfloat16*)p_wf2a, nullptr, nullptr,
        nullptr, (__nv_bfloat16*)p_t2b, N_TOK, 96, 768);
    bgemm_kernel<false><<<dim3(3, N_TOK / 128), 256>>>(
        (const __nv_bfloat16*)p_t2b, (const __nv_bfloat16*)p_wf2b, fc2_Bb, (const float*)p_x1,
        out, nullptr, N_TOK, 192, 96);
}

// round 10
// speedup vs baseline: 2.1931x; 1.2978x over previous
#include <cuda_runtime.h>
#include <cuda_bf16.h>
#include <math.h>
#include <cstdint>

#define N_TOK 65536
#define CDIM 192
#define HIDDEN 768
#define R1 384
#define R2 96

// ---------------- scratch (device globals; no allocation) ----------------
__device__ float g_qkv [N_TOK * 3 * CDIM]; // window-ordered qkv (fp32 for softmax accuracy)
__device__ float g_x1  [N_TOK * CDIM];     // after attn residual (token order, fp32)
__device__ float g_hmid[N_TOK * HIDDEN];   // fc1 out (fp32 for dwconv)

__device__ __nv_bfloat16 g_xn_b   [N_TOK * CDIM];   // LN1 out (window order)
__device__ __nv_bfloat16 g_x1n_b  [N_TOK * CDIM];   // LN2 out
__device__ __nv_bfloat16 g_attn_b [N_TOK * CDIM];   // attention out (window order)
__device__ __nv_bfloat16 g_t1_b   [N_TOK * R1];
__device__ __nv_bfloat16 g_hconv_b[N_TOK * HIDDEN];
__device__ __nv_bfloat16 g_t2_b   [N_TOK * R2];

// transposed bf16 weights Wt[N][K]
__device__ __nv_bfloat16 g_wqkv_t [576 * 192];
__device__ __nv_bfloat16 g_wproj_t[192 * 192];
__device__ __nv_bfloat16 g_wfc1A_t[384 * 192];
__device__ __nv_bfloat16 g_wfc1B_t[768 * 384];
__device__ __nv_bfloat16 g_wfc2A_t[96 * 768];
__device__ __nv_bfloat16 g_wfc2B_t[192 * 96];

// window-ordered index p -> token index n  (D=16,H=64,W=64, window 4x8x8)
__device__ __forceinline__ int p_to_n(int p) {
    int win = p >> 8, t = p & 255;
    int wd = win >> 6, wh = (win >> 3) & 7, ww = win & 7;
    int td = t >> 6,  th = (t >> 3) & 7,  tw = t & 7;
    int d = wd * 4 + td, h = wh * 8 + th, w = ww * 8 + tw;
    return (d << 12) + (h << 6) + w;
}

// ---------------- weight convert + transpose: W[K,N] fp32 -> Wt[N,K] bf16 ----------------
__global__ void convert_wt(const float* __restrict__ W, __nv_bfloat16* __restrict__ Wt,
                           int K, int N)
{
    int idx = blockIdx.x * 256 + threadIdx.x;
    if (idx < K * N) {
        int k = idx / N, n = idx - k * N;
        Wt[n * K + k] = __float2bfloat16(W[idx]);
    }
}

// ---------------- LayerNorm: 1 warp per token, bf16 out ----------------
template <bool PERM_IN>
__global__ void ln_kernel(const float* __restrict__ in, const float* __restrict__ gamma,
                          const float* __restrict__ beta, __nv_bfloat16* __restrict__ out)
{
    int warp = threadIdx.x >> 5, lane = threadIdx.x & 31;
    int p = blockIdx.x * 8 + warp;
    int n = PERM_IN ? p_to_n(p) : p;
    const float* row = in + (size_t)n * CDIM;
    float v[6]; float s = 0.f, sq = 0.f;
#pragma unroll
    for (int i = 0; i < 6; i++) { float x = row[lane + 32 * i]; v[i] = x; s += x; sq += x * x; }
#pragma unroll
    for (int o = 16; o > 0; o >>= 1) {
        s  += __shfl_xor_sync(0xffffffffu, s,  o);
        sq += __shfl_xor_sync(0xffffffffu, sq, o);
    }
    float mu = s * (1.f / CDIM);
    float var = sq * (1.f / CDIM) - mu * mu;
    float rs = rsqrtf(var + 1e-5f);
    __nv_bfloat16* orow = out + (size_t)p * CDIM;
#pragma unroll
    for (int i = 0; i < 6; i++) {
        int c = lane + 32 * i;
        orow[c] = __float2bfloat16((v[i] - mu) * rs * gamma[c] + beta[c]);
    }
}

// ---------------- bf16 tensor-core GEMM ----------------
// C[M,Nc] (fp32, optional) / Cb[M,Nc] (bf16, optional) = A[M,K]bf16 @ Wt[Nc,K]bf16^T
// + bias (fp32) + resid (fp32). PERMUTE remaps output row p->n (and resid read).
// BM=128 BN=64 BK=32; 8 warps (4 m x 2 n), warp tile 32x32 = 2x4 m16n8k16 MMAs.
#define SM_STRIDE32 20   // 40 bf16 per row = 20 words (conflict-free fragment reads)

#define MMA16816(d, a, b)                                                     \
    asm volatile("mma.sync.aligned.m16n8k16.row.col.f32.bf16.bf16.f32 "       \
                 "{%0,%1,%2,%3}, {%4,%5,%6,%7}, {%8,%9}, {%0,%1,%2,%3};"      \
                 : "+f"(d[0]), "+f"(d[1]), "+f"(d[2]), "+f"(d[3])             \
                 : "r"(a[0]), "r"(a[1]), "r"(a[2]), "r"(a[3]),                 \
                   "r"(b[0]), "r"(b[1]))

template <bool PERMUTE>
__global__ void __launch_bounds__(256) bgemm_kernel(
    const __nv_bfloat16* __restrict__ A, const __nv_bfloat16* __restrict__ Wt,
    const float* __restrict__ bias, const float* __restrict__ resid,
    float* __restrict__ C, __nv_bfloat16* __restrict__ Cb,
    int M, int Ncols, int K)
{
    __shared__ unsigned int As32[128 * SM_STRIDE32];
    __shared__ unsigned int Bs32[64 * SM_STRIDE32];

    int tid  = threadIdx.x;
    int lane = tid & 31;
    int warp = tid >> 5;
    int wm = warp >> 1;           // 0..3, 32 rows each
    int wn = warp & 1;            // 0..1, 32 cols each
    int g  = lane >> 2;           // 0..7
    int tg = lane & 3;            // 0..3

    int row0 = blockIdx.y * 128;
    int col0 = blockIdx.x * 64;

    float acc[2][4][4];
#pragma unroll
    for (int t = 0; t < 2; t++)
#pragma unroll
        for (int u = 0; u < 4; u++)
#pragma unroll
            for (int i = 0; i < 4; i++) acc[t][u][i] = 0.f;

    int br = tid >> 2, bseg = tid & 3;
    int bcol = col0 + br;

    for (int k0 = 0; k0 < K; k0 += 32) {
#pragma unroll
        for (int i = 0; i < 2; i++) {
            int s = tid + i * 256;
            int r = s >> 2, seg = s & 3;
            uint4 v = *(const uint4*)(A + (size_t)(row0 + r) * K + k0 + seg * 8);
            ((uint4*)As32)[r * 5 + seg] = v;
        }
        {
            uint4 v = make_uint4(0u, 0u, 0u, 0u);
            if (bcol < Ncols)
                v = *(const uint4*)(Wt + (size_t)bcol * K + k0 + bseg * 8);
            ((uint4*)Bs32)[br * 5 + bseg] = v;
        }
        __syncthreads();

#pragma unroll
        for (int ks = 0; ks < 2; ks++) {
            unsigned int a[2][4], b[4][2];
#pragma unroll
            for (int t = 0; t < 2; t++) {
                int base = (wm * 32 + t * 16 + g) * SM_STRIDE32 + ks * 8 + tg;
                a[t][0] = As32[base];
                a[t][1] = As32[base + 8 * SM_STRIDE32];
                a[t][2] = As32[base + 4];
                a[t][3] = As32[base + 8 * SM_STRIDE32 + 4];
            }
#pragma unroll
            for (int u = 0; u < 4; u++) {
                int base = (wn * 32 + u * 8 + g) * SM_STRIDE32 + ks * 8 + tg;
                b[u][0] = Bs32[base];
                b[u][1] = Bs32[base + 4];
            }
#pragma unroll
            for (int t = 0; t < 2; t++)
#pragma unroll
                for (int u = 0; u < 4; u++)
                    MMA16816(acc[t][u], a[t], b[u]);
        }
        __syncthreads();
    }

    // epilogue
#pragma unroll
    for (int t = 0; t < 2; t++) {
        int rlo = row0 + wm * 32 + t * 16 + g;
#pragma unroll
        for (int h2 = 0; h2 < 2; h2++) {
            int r = rlo + h2 * 8;
            int orow = PERMUTE ? p_to_n(r) : r;
            size_t ro = (size_t)orow * Ncols;
#pragma unroll
            for (int u = 0; u < 4; u++) {
                int c = col0 + wn * 32 + u * 8 + 2 * tg;
                if (c < Ncols) {
                    float v0 = acc[t][u][h2 * 2 + 0];
                    float v1 = acc[t][u][h2 * 2 + 1];
                    if (bias)  { v0 += bias[c]; v1 += bias[c + 1]; }
                    if (resid) { float2 rv = *(const float2*)(resid + ro + c);
                                 v0 += rv.x; v1 += rv.y; }
                    if (C)  *(float2*)(C + ro + c) = make_float2(v0, v1);
                    if (Cb) *(__nv_bfloat162*)(Cb + ro + c) = __floats2bfloat162_rn(v0, v1);
                }
            }
        }
    }
}

// ---------------- windowed attention: one block per (head, window) ----------------
__global__ void __launch_bounds__(256) attn_kernel(const float* __restrict__ rel_bias)
{
    extern __shared__ float sm[];
    float* Ks = sm;            // 256*32
    float* Vs = sm + 8192;     // 256*32
    int*   grp = (int*)(sm + 16384);
    int*   fjs = grp + 256;
    int head = blockIdx.x, win = blockIdx.y;
    int tid = threadIdx.x;
    size_t base = (size_t)(win * 256) * 576 + head * 32;

    for (int i = tid; i < 8192; i += 256) {
        int r = i >> 5, c = i & 31;
        Ks[i] = g_qkv[base + (size_t)r * 576 + c];
    }
    __syncthreads();
    float q[32];
#pragma unroll
    for (int c = 0; c < 32; c++) q[c] = Ks[tid * 32 + c] * 0.17677669529663687f;
    __syncthreads();
    for (int i = tid; i < 8192; i += 256) {
        int r = i >> 5, c = i & 31;
        Ks[i] = g_qkv[base + 192 + (size_t)r * 576 + c];
        Vs[i] = g_qkv[base + 384 + (size_t)r * 576 + c];
    }
    {
        int t = tid;
        int wd = win >> 6, wh = (win >> 3) & 7, ww = win & 7;
        int td = t >> 6, th = (t >> 3) & 7, tw = t & 7;
        int d = wd * 4 + td, h = wh * 8 + th, w = ww * 8 + tw;
        int gd = (d + 2) & 15, gh = (h + 4) & 63, gw = (w + 4) & 63;
        grp[t] = (gd >> 2) * 64 + (gh >> 3) * 8 + (gw >> 3);
        fjs[t] = td * 225 + th * 15 + tw;
    }
    __syncthreads();

    int gi = grp[tid];
    int fi = fjs[tid] + 787;
    float m = -1e30f, l = 0.f;
    float o[32];
#pragma unroll
    for (int c = 0; c < 32; c++) o[c] = 0.f;

    for (int j = 0; j < 256; j++) {
        const float4* kr = (const float4*)(Ks + j * 32);
        float s = 0.f;
#pragma unroll
        for (int c4 = 0; c4 < 8; c4++) {
            float4 kv = kr[c4];
            s = fmaf(q[c4 * 4 + 0], kv.x, s); s = fmaf(q[c4 * 4 + 1], kv.y, s);
            s = fmaf(q[c4 * 4 + 2], kv.z, s); s = fmaf(q[c4 * 4 + 3], kv.w, s);
        }
        int ridx = fi - fjs[j];
        s += __ldg(&rel_bias[ridx * 6 + head]);
        if (grp[j] != gi) s -= 100.f;

        if (s > m) {
            float corr = __expf(m - s);
            l *= corr;
#pragma unroll
            for (int c = 0; c < 32; c++) o[c] *= corr;
            m = s;
        }
        float pexp = __expf(s - m);
        l += pexp;
        const float4* vr = (const float4*)(Vs + j * 32);
#pragma unroll
        for (int c4 = 0; c4 < 8; c4++) {
            float4 vv = vr[c4];
            o[c4 * 4 + 0] = fmaf(pexp, vv.x, o[c4 * 4 + 0]);
            o[c4 * 4 + 1] = fmaf(pexp, vv.y, o[c4 * 4 + 1]);
            o[c4 * 4 + 2] = fmaf(pexp, vv.z, o[c4 * 4 + 2]);
            o[c4 * 4 + 3] = fmaf(pexp, vv.w, o[c4 * 4 + 3]);
        }
    }
    float inv = 1.f / l;
    __nv_bfloat162* ow = (__nv_bfloat162*)(g_attn_b + (size_t)(win * 256 + tid) * 192 + head * 32);
#pragma unroll
    for (int c2 = 0; c2 < 16; c2++)
        ow[c2] = __floats2bfloat162_rn(o[2 * c2] * inv, o[2 * c2 + 1] * inv);
}

// ---------------- depthwise conv3d 3x3x3 + bias + exact GELU (bf16 out) ----------------
// Grid: 1024 (d,h) rows x 3 channel-chunks. 256 threads = 256 channels.
// Each thread keeps its 27 weights in registers and slides a 3x3x3 window
// along w (9 new loads per step, coalesced across channels).
__global__ void __launch_bounds__(256) dwconv_gelu_kernel(
    const float* __restrict__ wgt, const float* __restrict__ bias)
{
    int bid = blockIdx.x;
    int chunk = bid % 3;
    int dh = bid / 3;            // 0..1023
    int d = dh >> 6, h = dh & 63;
    int c = chunk * 256 + threadIdx.x;

    float wr[27];
#pragma unroll
    for (int i = 0; i < 27; i++) wr[i] = wgt[c * 27 + i];
    float bv = bias[c];

    // validity of the 9 (kd,kh) taps
    bool dv[3], hv[3];
    dv[0] = (d - 1) >= 0; dv[1] = true; dv[2] = (d + 1) < 16;
    hv[0] = (h - 1) >= 0; hv[1] = true; hv[2] = (h + 1) < 64;

    // row base offsets for the 9 taps (element index of (dd,hh,0))
    int rbase[9];
#pragma unroll
    for (int kd = 0; kd < 3; kd++)
#pragma unroll
        for (int kh = 0; kh < 3; kh++)
            rbase[kd * 3 + kh] = ((d + kd - 1) << 12) + ((h + kh - 1) << 6);

    // plane registers: pl0 = w-1, pl1 = w, pl2 = w+1; each 9 taps
    float pl0[9], pl1[9], pl2[9];
#pragma unroll
    for (int i = 0; i < 9; i++) pl0[i] = 0.f;   // w=-1 out of range
#pragma unroll
    for (int i = 0; i < 9; i++) {
        bool v = dv[i / 3] && hv[i % 3];
        pl1[i] = v ? g_hmid[(size_t)(rbase[i] + 0) * 768 + c] : 0.f;
        pl2[i] = v ? g_hmid[(size_t)(rbase[i] + 1) * 768 + c] : 0.f;
    }

    size_t obase = ((size_t)((d << 12) + (h << 6)) ) * 768 + c;

    for (int w = 0; w < 64; w++) {
        float acc = bv;
#pragma unroll
        for (int i = 0; i < 9; i++) {
            acc = fmaf(pl0[i], wr[i * 3 + 0], acc);
            acc = fmaf(pl1[i], wr[i * 3 + 1], acc);
            acc = fmaf(pl2[i], wr[i * 3 + 2], acc);
        }
        float gel = 0.5f * acc * (1.f + erff(acc * 0.70710678118654752440f));
        g_hconv_b[obase + (size_t)w * 768] = __float2bfloat16(gel);

        // slide: load w+2 plane
#pragma unroll
        for (int i = 0; i < 9; i++) { pl0[i] = pl1[i]; pl1[i] = pl2[i]; }
        if (w + 2 < 64) {
#pragma unroll
            for (int i = 0; i < 9; i++) {
                bool v = dv[i / 3] && hv[i % 3];
                pl2[i] = v ? g_hmid[(size_t)(rbase[i] + w + 2) * 768 + c] : 0.f;
            }
        } else {
#pragma unroll
            for (int i = 0; i < 9; i++) pl2[i] = 0.f;
        }
    }
}

// ---------------- host ----------------
extern "C" void kernel_launch(void* const* d_in, const int* in_sizes, int n_in,
                              void* d_out, int out_size)
{
    (void)in_sizes; (void)n_in; (void)out_size;
    const float* x       = (const float*)d_in[0];
    const float* n1g     = (const float*)d_in[1];
    const float* n1b     = (const float*)d_in[2];
    const float* qkv_w   = (const float*)d_in[3];
    const float* qkv_b   = (const float*)d_in[4];
    const float* rel_b   = (const float*)d_in[5];
    const float* proj_w  = (const float*)d_in[6];
    const float* proj_b  = (const float*)d_in[7];
    const float* n2g     = (const float*)d_in[8];
    const float* n2b     = (const float*)d_in[9];
    const float* fc1_A   = (const float*)d_in[10];
    const float* fc1_Bw  = (const float*)d_in[11];
    const float* fc1_Bb  = (const float*)d_in[12];
    const float* dw_w    = (const float*)d_in[13];
    const float* dw_b    = (const float*)d_in[14];
    const float* fc2_A   = (const float*)d_in[15];
    const float* fc2_Bw  = (const float*)d_in[16];
    const float* fc2_Bb  = (const float*)d_in[17];
    float* out = (float*)d_out;

    void *p_qkv, *p_x1, *p_hmid;
    void *p_xnb, *p_x1nb, *p_attnb, *p_t1b, *p_hcb, *p_t2b;
    void *p_wqkv, *p_wproj, *p_wf1a, *p_wf1b, *p_wf2a, *p_wf2b;
    cudaGetSymbolAddress(&p_qkv, g_qkv);   cudaGetSymbolAddress(&p_x1, g_x1);
    cudaGetSymbolAddress(&p_hmid, g_hmid);
    cudaGetSymbolAddress(&p_xnb, g_xn_b);  cudaGetSymbolAddress(&p_x1nb, g_x1n_b);
    cudaGetSymbolAddress(&p_attnb, g_attn_b); cudaGetSymbolAddress(&p_t1b, g_t1_b);
    cudaGetSymbolAddress(&p_hcb, g_hconv_b);  cudaGetSymbolAddress(&p_t2b, g_t2_b);
    cudaGetSymbolAddress(&p_wqkv, g_wqkv_t);  cudaGetSymbolAddress(&p_wproj, g_wproj_t);
    cudaGetSymbolAddress(&p_wf1a, g_wfc1A_t); cudaGetSymbolAddress(&p_wf1b, g_wfc1B_t);
    cudaGetSymbolAddress(&p_wf2a, g_wfc2A_t); cudaGetSymbolAddress(&p_wf2b, g_wfc2B_t);

    // 0) weight convert + transpose (tiny)
    convert_wt<<<(192*576 + 255)/256, 256>>>(qkv_w,  (__nv_bfloat16*)p_wqkv, 192, 576);
    convert_wt<<<(192*192 + 255)/256, 256>>>(proj_w, (__nv_bfloat16*)p_wproj, 192, 192);
    convert_wt<<<(192*384 + 255)/256, 256>>>(fc1_A,  (__nv_bfloat16*)p_wf1a, 192, 384);
    convert_wt<<<(384*768 + 255)/256, 256>>>(fc1_Bw, (__nv_bfloat16*)p_wf1b, 384, 768);
    convert_wt<<<(768*96  + 255)/256, 256>>>(fc2_A,  (__nv_bfloat16*)p_wf2a, 768, 96);
    convert_wt<<<(96*192  + 255)/256, 256>>>(fc2_Bw, (__nv_bfloat16*)p_wf2b, 96, 192);

    // 1) LN1 (read-permuted into window order), bf16 out
    ln_kernel<true><<<N_TOK / 8, 256>>>(x, n1g, n1b, (__nv_bfloat16*)p_xnb);
    // 2) QKV gemm -> fp32
    bgemm_kernel<false><<<dim3(9, N_TOK / 128), 256>>>(
        (const __nv_bfloat16*)p_xnb, (const __nv_bfloat16*)p_wqkv, qkv_b, nullptr,
        (float*)p_qkv, nullptr, N_TOK, 576, 192);
    // 3) attention -> bf16
    const int SMEM_ATTN = (8192 + 8192 + 256 + 256) * 4;
    cudaFuncSetAttribute(attn_kernel, cudaFuncAttributeMaxDynamicSharedMemorySize, SMEM_ATTN);
    attn_kernel<<<dim3(6, 256), 256, SMEM_ATTN>>>(rel_b);
    // 4) proj + residual (+ un-window permute on write) -> fp32
    bgemm_kernel<true><<<dim3(3, N_TOK / 128), 256>>>(
        (const __nv_bfloat16*)p_attnb, (const __nv_bfloat16*)p_wproj, proj_b, x,
        (float*)p_x1, nullptr, N_TOK, 192, 192);
    // 5) LN2 -> bf16
    ln_kernel<false><<<N_TOK / 8, 256>>>((const float*)p_x1, n2g, n2b, (__nv_bfloat16*)p_x1nb);
    // 6) fc1 low-rank
    bgemm_kernel<false><<<dim3(6, N_TOK / 128), 256>>>(
        (const __nv_bfloat16*)p_x1nb, (const __nv_bfloat16*)p_wf1a, nullptr, nullptr,
        nullptr, (__nv_bfloat16*)p_t1b, N_TOK, 384, 192);
    bgemm_kernel<false><<<dim3(12, N_TOK / 128), 256>>>(
        (const __nv_bfloat16*)p_t1b, (const __nv_bfloat16*)p_wf1b, fc1_Bb, nullptr,
        (float*)p_hmid, nullptr, N_TOK, 768, 384);
    // 7) depthwise conv + GELU -> bf16 (register-resident weights, slide along w)
    dwconv_gelu_kernel<<<1024 * 3, 256>>>(dw_w, dw_b);
    // 8) fc2 low-rank + final residual
    bgemm_kernel<false><<<dim3(2, N_TOK / 128), 256>>>(
        (const __nv_bfloat16*)p_hcb, (const __nv_bfloat16*)p_wf2a, nullptr, nullptr,
        nullptr, (__nv_bfloat16*)p_t2b, N_TOK, 96, 768);
    bgemm_kernel<false><<<dim3(3, N_TOK / 128), 256>>>(
        (const __nv_bfloat16*)p_t2b, (const __nv_bfloat16*)p_wf2b, fc2_Bb, (const float*)p_x1,
        out, nullptr, N_TOK, 192, 96);
}